// round 2
// baseline (speedup 1.0000x reference)
#include <cuda_runtime.h>
#include <math.h>

// ---------------------------------------------------------------------------
// Problem constants
// ---------------------------------------------------------------------------
namespace {
constexpr int kB = 4;
constexpr int kN = 2048;
constexpr int kD = 1024;
constexpr int kH = 16;
constexpr int kHD = 64;
constexpr int kInner = kH * kHD;        // 1024
constexpr int kRows = kB * kN;          // 8192
constexpr int kQKV = 3 * kInner;        // 3072
}

// Scratch (static device globals; no allocation allowed)
__device__ float g_xn[kRows * kD];                 // 32 MB
__device__ float g_qkv[(size_t)kRows * kQKV];      // 96 MB
__device__ float g_attn[kRows * kInner];           // 32 MB

// ---------------------------------------------------------------------------
// LayerNorm: one block per row (D=1024, 256 threads, float4)
// ---------------------------------------------------------------------------
__global__ __launch_bounds__(256) void ln_kernel(
    const float* __restrict__ x, const float* __restrict__ gamma,
    const float* __restrict__ beta, float* __restrict__ xn) {
  const int row = blockIdx.x;
  const float* xr = x + (size_t)row * kD;
  const int i4 = threadIdx.x * 4;

  float4 v = *(const float4*)(xr + i4);
  float sum = v.x + v.y + v.z + v.w;
  float sq = v.x * v.x + v.y * v.y + v.z * v.z + v.w * v.w;

  __shared__ float s1[8], s2[8];
#pragma unroll
  for (int o = 16; o; o >>= 1) {
    sum += __shfl_xor_sync(0xffffffffu, sum, o);
    sq  += __shfl_xor_sync(0xffffffffu, sq, o);
  }
  const int w = threadIdx.x >> 5, l = threadIdx.x & 31;
  if (l == 0) { s1[w] = sum; s2[w] = sq; }
  __syncthreads();
  if (w == 0) {
    sum = (l < 8) ? s1[l] : 0.f;
    sq  = (l < 8) ? s2[l] : 0.f;
#pragma unroll
    for (int o = 4; o; o >>= 1) {
      sum += __shfl_xor_sync(0xffffffffu, sum, o);
      sq  += __shfl_xor_sync(0xffffffffu, sq, o);
    }
    if (l == 0) { s1[0] = sum; s2[0] = sq; }
  }
  __syncthreads();
  const float mu = s1[0] * (1.f / kD);
  const float var = s2[0] * (1.f / kD) - mu * mu;
  const float inv = rsqrtf(var + 1e-5f);

  float4 g = *(const float4*)(gamma + i4);
  float4 bt = *(const float4*)(beta + i4);
  float4 o;
  o.x = (v.x - mu) * inv * g.x + bt.x;
  o.y = (v.y - mu) * inv * g.y + bt.y;
  o.z = (v.z - mu) * inv * g.z + bt.z;
  o.w = (v.w - mu) * inv * g.w + bt.w;
  *(float4*)(xn + (size_t)row * kD + i4) = o;
}

// ---------------------------------------------------------------------------
// SGEMM: C[M,Nn] = A[M,K] * B[K,Nn] (+bias). 128x128 tile, 256 thr, 8x8/thr.
// All dims multiples of 128 / K multiple of 8; no bounds checks needed.
// ---------------------------------------------------------------------------
template <bool WITH_BIAS>
__global__ __launch_bounds__(256) void sgemm128(
    const float* __restrict__ A, const float* __restrict__ Bm,
    float* __restrict__ C, const float* __restrict__ bias,
    int M, int Nn, int K) {
  __shared__ float As[8][128];
  __shared__ float Bs[8][128];

  const int tid = threadIdx.x;
  const int tm = (tid >> 4) * 8;        // 0..120
  const int tn = (tid & 15) * 8;        // 0..120
  const int bm = blockIdx.y * 128;
  const int bn = blockIdx.x * 128;

  const int arow = tid >> 1;            // 0..127
  const int acol = (tid & 1) * 4;       // 0 or 4
  const int brow = tid >> 5;            // 0..7
  const int bcol = (tid & 31) * 4;      // 0..124

  const float* Aptr = A + (size_t)(bm + arow) * K + acol;
  const float* Bptr = Bm + (size_t)brow * Nn + bn + bcol;

  float acc[8][8];
#pragma unroll
  for (int i = 0; i < 8; i++)
#pragma unroll
    for (int j = 0; j < 8; j++) acc[i][j] = 0.f;

  for (int k0 = 0; k0 < K; k0 += 8) {
    float4 a4 = *(const float4*)(Aptr + k0);
    float4 b4 = *(const float4*)(Bptr + (size_t)k0 * Nn);
    As[acol + 0][arow] = a4.x;
    As[acol + 1][arow] = a4.y;
    As[acol + 2][arow] = a4.z;
    As[acol + 3][arow] = a4.w;
    *(float4*)&Bs[brow][bcol] = b4;
    __syncthreads();
#pragma unroll
    for (int kk = 0; kk < 8; kk++) {
      float af[8], bf[8];
#pragma unroll
      for (int i = 0; i < 8; i++) af[i] = As[kk][tm + i];
#pragma unroll
      for (int j = 0; j < 8; j++) bf[j] = Bs[kk][tn + j];
#pragma unroll
      for (int i = 0; i < 8; i++)
#pragma unroll
        for (int j = 0; j < 8; j++) acc[i][j] = fmaf(af[i], bf[j], acc[i][j]);
    }
    __syncthreads();
  }

#pragma unroll
  for (int i = 0; i < 8; i++) {
    const size_t crow = (size_t)(bm + tm + i) * Nn + bn + tn;
#pragma unroll
    for (int j = 0; j < 8; j += 4) {
      float4 v = make_float4(acc[i][j], acc[i][j + 1], acc[i][j + 2], acc[i][j + 3]);
      if (WITH_BIAS) {
        v.x += bias[bn + tn + j + 0];
        v.y += bias[bn + tn + j + 1];
        v.z += bias[bn + tn + j + 2];
        v.w += bias[bn + tn + j + 3];
      }
      *(float4*)&C[crow + j] = v;
    }
  }
}

// ---------------------------------------------------------------------------
// RoPE: in-place on q and k parts of qkv. One block per (b,n) row.
// pair (i, i+32) per head, i in [0,32).
// ---------------------------------------------------------------------------
__global__ __launch_bounds__(256) void rope_kernel(float* __restrict__ qkv) {
  const int row = blockIdx.x;          // 0..8191
  const int n = row & (kN - 1);
  __shared__ float invf[32];
  if (threadIdx.x < 32)
    invf[threadIdx.x] = powf(10000.0f, -(float)threadIdx.x / 32.0f);
  __syncthreads();

  float* base = qkv + (size_t)row * kQKV;
  for (int idx = threadIdx.x; idx < kH * 32; idx += blockDim.x) {
    const int h = idx >> 5;
    const int i = idx & 31;
    float s, c;
    sincosf((float)n * invf[i], &s, &c);
    float* q = base + h * kHD;
    float t1 = q[i], t2 = q[i + 32];
    q[i] = t1 * c - t2 * s;
    q[i + 32] = t2 * c + t1 * s;
    float* k = base + kInner + h * kHD;
    t1 = k[i]; t2 = k[i + 32];
    k[i] = t1 * c - t2 * s;
    k[i + 32] = t2 * c + t1 * s;
  }
}

// ---------------------------------------------------------------------------
// Attention: one thread per query row; 128 query rows per block;
// K/V tiles of 64 rows in smem (32 KB); streaming online softmax.
// ---------------------------------------------------------------------------
__global__ __launch_bounds__(128) void attn_kernel(
    const float* __restrict__ qkv, float* __restrict__ attn_out) {
  __shared__ float Ks[64][64];
  __shared__ float Vs[64][64];

  const int qt = blockIdx.x;           // 0..15
  const int bh = blockIdx.y;           // 0..63
  const int b = bh >> 4;
  const int h = bh & 15;
  const int t = threadIdx.x;
  const int qi = qt * 128 + t;

  const float* qp = qkv + (size_t)(b * kN + qi) * kQKV + h * kHD;
  float q[kHD], O[kHD];
#pragma unroll
  for (int d = 0; d < kHD; d++) { q[d] = qp[d]; O[d] = 0.f; }
  float m = -1e30f, l = 0.f;

  for (int kt = 0; kt < kN / 64; kt++) {
    __syncthreads();  // protect previous tile from overwrite
    const float* kbase = qkv + (size_t)(b * kN + kt * 64) * kQKV + h * kHD;
#pragma unroll
    for (int it = 0; it < 8; it++) {
      const int idx = it * 128 + t;    // 0..1023
      const int r = idx >> 4;
      const int c = (idx & 15) * 4;
      *(float4*)&Ks[r][c] = *(const float4*)(kbase + (size_t)r * kQKV + kInner + c);
      *(float4*)&Vs[r][c] = *(const float4*)(kbase + (size_t)r * kQKV + 2 * kInner + c);
    }
    __syncthreads();

    for (int j = 0; j < 64; j++) {
      float s0 = 0.f, s1 = 0.f, s2 = 0.f, s3 = 0.f;
#pragma unroll
      for (int d = 0; d < kHD; d += 4) {
        s0 = fmaf(q[d + 0], Ks[j][d + 0], s0);
        s1 = fmaf(q[d + 1], Ks[j][d + 1], s1);
        s2 = fmaf(q[d + 2], Ks[j][d + 2], s2);
        s3 = fmaf(q[d + 3], Ks[j][d + 3], s3);
      }
      float s = ((s0 + s1) + (s2 + s3)) * 0.125f;   // * HD^-0.5
      if (s > m) {
        const float corr = __expf(m - s);
        l *= corr;
#pragma unroll
        for (int d = 0; d < kHD; d++) O[d] *= corr;
        m = s;
      }
      const float p = __expf(s - m);
      l += p;
#pragma unroll
      for (int d = 0; d < kHD; d++) O[d] = fmaf(p, Vs[j][d], O[d]);
    }
  }

  const float invl = 1.f / l;
  float* op = attn_out + (size_t)(b * kN + qi) * kInner + h * kHD;
#pragma unroll
  for (int d = 0; d < kHD; d++) op[d] = O[d] * invl;
}

// ---------------------------------------------------------------------------
// Launch
// ---------------------------------------------------------------------------
extern "C" void kernel_launch(void* const* d_in, const int* in_sizes, int n_in,
                              void* d_out, int out_size) {
  const float* x      = (const float*)d_in[0];
  const float* gamma  = (const float*)d_in[1];
  const float* beta   = (const float*)d_in[2];
  const float* w_qkv  = (const float*)d_in[3];
  const float* w_out  = (const float*)d_in[4];
  const float* b_out  = (const float*)d_in[5];
  float* out = (float*)d_out;

  void* p;
  cudaGetSymbolAddress(&p, g_xn);
  float* xn = (float*)p;
  cudaGetSymbolAddress(&p, g_qkv);
  float* qkv = (float*)p;
  cudaGetSymbolAddress(&p, g_attn);
  float* attn = (float*)p;

  ln_kernel<<<kRows, 256>>>(x, gamma, beta, xn);

  sgemm128<false><<<dim3(kQKV / 128, kRows / 128), 256>>>(
      xn, w_qkv, qkv, nullptr, kRows, kQKV, kD);

  rope_kernel<<<kRows, 256>>>(qkv);

  attn_kernel<<<dim3(kN / 128, kB * kH), 128>>>(qkv, attn);

  sgemm128<true><<<dim3(kD / 128, kRows / 128), 256>>>(
      attn, w_out, out, b_out, kRows, kD, kInner);
}

// round 3
// speedup vs baseline: 1.0003x; 1.0003x over previous
#include <cuda_runtime.h>
#include <math.h>

// ---------------------------------------------------------------------------
// Problem constants
// ---------------------------------------------------------------------------
namespace {
constexpr int kB = 4;
constexpr int kN = 2048;
constexpr int kD = 1024;
constexpr int kH = 16;
constexpr int kHD = 64;
constexpr int kInner = kH * kHD;        // 1024
constexpr int kRows = kB * kN;          // 8192
constexpr int kQKV = 3 * kInner;        // 3072
}

// Scratch (static device globals; no allocation allowed)
__device__ float g_xn[kRows * kD];                 // 32 MB
__device__ float g_qkv[(size_t)kRows * kQKV];      // 96 MB
__device__ float g_attn[kRows * kInner];           // 32 MB

// ---------------------------------------------------------------------------
// LayerNorm: one block per row (D=1024, 256 threads, float4)
// ---------------------------------------------------------------------------
__global__ __launch_bounds__(256) void ln_kernel(
    const float* __restrict__ x, const float* __restrict__ gamma,
    const float* __restrict__ beta, float* __restrict__ xn) {
  const int row = blockIdx.x;
  const float* xr = x + (size_t)row * kD;
  const int i4 = threadIdx.x * 4;

  float4 v = *(const float4*)(xr + i4);
  float sum = v.x + v.y + v.z + v.w;
  float sq = v.x * v.x + v.y * v.y + v.z * v.z + v.w * v.w;

  __shared__ float s1[8], s2[8];
#pragma unroll
  for (int o = 16; o; o >>= 1) {
    sum += __shfl_xor_sync(0xffffffffu, sum, o);
    sq  += __shfl_xor_sync(0xffffffffu, sq, o);
  }
  const int w = threadIdx.x >> 5, l = threadIdx.x & 31;
  if (l == 0) { s1[w] = sum; s2[w] = sq; }
  __syncthreads();
  if (w == 0) {
    sum = (l < 8) ? s1[l] : 0.f;
    sq  = (l < 8) ? s2[l] : 0.f;
#pragma unroll
    for (int o = 4; o; o >>= 1) {
      sum += __shfl_xor_sync(0xffffffffu, sum, o);
      sq  += __shfl_xor_sync(0xffffffffu, sq, o);
    }
    if (l == 0) { s1[0] = sum; s2[0] = sq; }
  }
  __syncthreads();
  const float mu = s1[0] * (1.f / kD);
  const float var = s2[0] * (1.f / kD) - mu * mu;
  const float inv = rsqrtf(var + 1e-5f);

  float4 g = *(const float4*)(gamma + i4);
  float4 bt = *(const float4*)(beta + i4);
  float4 o;
  o.x = (v.x - mu) * inv * g.x + bt.x;
  o.y = (v.y - mu) * inv * g.y + bt.y;
  o.z = (v.z - mu) * inv * g.z + bt.z;
  o.w = (v.w - mu) * inv * g.w + bt.w;
  *(float4*)(xn + (size_t)row * kD + i4) = o;
}

// ---------------------------------------------------------------------------
// SGEMM: C[M,Nn] = A[M,K] * B[K,Nn] (+bias). 128x128 tile, 256 thr, 8x8/thr.
// All dims multiples of 128 / K multiple of 8; no bounds checks needed.
// ---------------------------------------------------------------------------
template <bool WITH_BIAS>
__global__ __launch_bounds__(256) void sgemm128(
    const float* __restrict__ A, const float* __restrict__ Bm,
    float* __restrict__ C, const float* __restrict__ bias,
    int M, int Nn, int K) {
  __shared__ float As[8][128];
  __shared__ float Bs[8][128];

  const int tid = threadIdx.x;
  const int tm = (tid >> 4) * 8;        // 0..120
  const int tn = (tid & 15) * 8;        // 0..120
  const int bm = blockIdx.y * 128;
  const int bn = blockIdx.x * 128;

  const int arow = tid >> 1;            // 0..127
  const int acol = (tid & 1) * 4;       // 0 or 4
  const int brow = tid >> 5;            // 0..7
  const int bcol = (tid & 31) * 4;      // 0..124

  const float* Aptr = A + (size_t)(bm + arow) * K + acol;
  const float* Bptr = Bm + (size_t)brow * Nn + bn + bcol;

  float acc[8][8];
#pragma unroll
  for (int i = 0; i < 8; i++)
#pragma unroll
    for (int j = 0; j < 8; j++) acc[i][j] = 0.f;

  for (int k0 = 0; k0 < K; k0 += 8) {
    float4 a4 = *(const float4*)(Aptr + k0);
    float4 b4 = *(const float4*)(Bptr + (size_t)k0 * Nn);
    As[acol + 0][arow] = a4.x;
    As[acol + 1][arow] = a4.y;
    As[acol + 2][arow] = a4.z;
    As[acol + 3][arow] = a4.w;
    *(float4*)&Bs[brow][bcol] = b4;
    __syncthreads();
#pragma unroll
    for (int kk = 0; kk < 8; kk++) {
      float af[8], bf[8];
#pragma unroll
      for (int i = 0; i < 8; i++) af[i] = As[kk][tm + i];
#pragma unroll
      for (int j = 0; j < 8; j++) bf[j] = Bs[kk][tn + j];
#pragma unroll
      for (int i = 0; i < 8; i++)
#pragma unroll
        for (int j = 0; j < 8; j++) acc[i][j] = fmaf(af[i], bf[j], acc[i][j]);
    }
    __syncthreads();
  }

#pragma unroll
  for (int i = 0; i < 8; i++) {
    const size_t crow = (size_t)(bm + tm + i) * Nn + bn + tn;
#pragma unroll
    for (int j = 0; j < 8; j += 4) {
      float4 v = make_float4(acc[i][j], acc[i][j + 1], acc[i][j + 2], acc[i][j + 3]);
      if (WITH_BIAS) {
        v.x += bias[bn + tn + j + 0];
        v.y += bias[bn + tn + j + 1];
        v.z += bias[bn + tn + j + 2];
        v.w += bias[bn + tn + j + 3];
      }
      *(float4*)&C[crow + j] = v;
    }
  }
}

// ---------------------------------------------------------------------------
// RoPE: in-place on q and k parts of qkv. One block per (b,n) row.
// pair (i, i+32) per head, i in [0,32).
// ---------------------------------------------------------------------------
__global__ __launch_bounds__(256) void rope_kernel(float* __restrict__ qkv) {
  const int row = blockIdx.x;          // 0..8191
  const int n = row & (kN - 1);
  __shared__ float invf[32];
  if (threadIdx.x < 32)
    invf[threadIdx.x] = powf(10000.0f, -(float)threadIdx.x / 32.0f);
  __syncthreads();

  float* base = qkv + (size_t)row * kQKV;
  for (int idx = threadIdx.x; idx < kH * 32; idx += blockDim.x) {
    const int h = idx >> 5;
    const int i = idx & 31;
    float s, c;
    sincosf((float)n * invf[i], &s, &c);
    float* q = base + h * kHD;
    float t1 = q[i], t2 = q[i + 32];
    q[i] = t1 * c - t2 * s;
    q[i + 32] = t2 * c + t1 * s;
    float* k = base + kInner + h * kHD;
    t1 = k[i]; t2 = k[i + 32];
    k[i] = t1 * c - t2 * s;
    k[i + 32] = t2 * c + t1 * s;
  }
}

// ---------------------------------------------------------------------------
// Attention: one thread per query row; 128 query rows per block;
// K/V tiles of 64 rows in smem (32 KB); streaming online softmax.
// ---------------------------------------------------------------------------
__global__ __launch_bounds__(128) void attn_kernel(
    const float* __restrict__ qkv, float* __restrict__ attn_out) {
  __shared__ float Ks[64][64];
  __shared__ float Vs[64][64];

  const int qt = blockIdx.x;           // 0..15
  const int bh = blockIdx.y;           // 0..63
  const int b = bh >> 4;
  const int h = bh & 15;
  const int t = threadIdx.x;
  const int qi = qt * 128 + t;

  const float* qp = qkv + (size_t)(b * kN + qi) * kQKV + h * kHD;
  float q[kHD], O[kHD];
#pragma unroll
  for (int d = 0; d < kHD; d++) { q[d] = qp[d]; O[d] = 0.f; }
  float m = -1e30f, l = 0.f;

  for (int kt = 0; kt < kN / 64; kt++) {
    __syncthreads();  // protect previous tile from overwrite
    const float* kbase = qkv + (size_t)(b * kN + kt * 64) * kQKV + h * kHD;
#pragma unroll
    for (int it = 0; it < 8; it++) {
      const int idx = it * 128 + t;    // 0..1023
      const int r = idx >> 4;
      const int c = (idx & 15) * 4;
      *(float4*)&Ks[r][c] = *(const float4*)(kbase + (size_t)r * kQKV + kInner + c);
      *(float4*)&Vs[r][c] = *(const float4*)(kbase + (size_t)r * kQKV + 2 * kInner + c);
    }
    __syncthreads();

    for (int j = 0; j < 64; j++) {
      float s0 = 0.f, s1 = 0.f, s2 = 0.f, s3 = 0.f;
#pragma unroll
      for (int d = 0; d < kHD; d += 4) {
        s0 = fmaf(q[d + 0], Ks[j][d + 0], s0);
        s1 = fmaf(q[d + 1], Ks[j][d + 1], s1);
        s2 = fmaf(q[d + 2], Ks[j][d + 2], s2);
        s3 = fmaf(q[d + 3], Ks[j][d + 3], s3);
      }
      float s = ((s0 + s1) + (s2 + s3)) * 0.125f;   // * HD^-0.5
      if (s > m) {
        const float corr = __expf(m - s);
        l *= corr;
#pragma unroll
        for (int d = 0; d < kHD; d++) O[d] *= corr;
        m = s;
      }
      const float p = __expf(s - m);
      l += p;
#pragma unroll
      for (int d = 0; d < kHD; d++) O[d] = fmaf(p, Vs[j][d], O[d]);
    }
  }

  const float invl = 1.f / l;
  float* op = attn_out + (size_t)(b * kN + qi) * kInner + h * kHD;
#pragma unroll
  for (int d = 0; d < kHD; d++) op[d] = O[d] * invl;
}

// ---------------------------------------------------------------------------
// Launch
// ---------------------------------------------------------------------------
extern "C" void kernel_launch(void* const* d_in, const int* in_sizes, int n_in,
                              void* d_out, int out_size) {
  const float* x      = (const float*)d_in[0];
  const float* gamma  = (const float*)d_in[1];
  const float* beta   = (const float*)d_in[2];
  const float* w_qkv  = (const float*)d_in[3];
  const float* w_out  = (const float*)d_in[4];
  const float* b_out  = (const float*)d_in[5];
  float* out = (float*)d_out;

  void* p;
  cudaGetSymbolAddress(&p, g_xn);
  float* xn = (float*)p;
  cudaGetSymbolAddress(&p, g_qkv);
  float* qkv = (float*)p;
  cudaGetSymbolAddress(&p, g_attn);
  float* attn = (float*)p;

  ln_kernel<<<kRows, 256>>>(x, gamma, beta, xn);

  sgemm128<false><<<dim3(kQKV / 128, kRows / 128), 256>>>(
      xn, w_qkv, qkv, nullptr, kRows, kQKV, kD);

  rope_kernel<<<kRows, 256>>>(qkv);

  attn_kernel<<<dim3(kN / 128, kB * kH), 128>>>(qkv, attn);

  sgemm128<true><<<dim3(kD / 128, kRows / 128), 256>>>(
      attn, w_out, out, b_out, kRows, kD, kInner);
}

// round 4
// speedup vs baseline: 1.0016x; 1.0013x over previous
#include <cuda_runtime.h>
#include <math.h>

// ---------------------------------------------------------------------------
// Problem constants
// ---------------------------------------------------------------------------
namespace {
constexpr int kB = 4;
constexpr int kN = 2048;
constexpr int kD = 1024;
constexpr int kH = 16;
constexpr int kHD = 64;
constexpr int kInner = kH * kHD;        // 1024
constexpr int kRows = kB * kN;          // 8192
constexpr int kQKV = 3 * kInner;        // 3072
}

// Scratch (static device globals; no allocation allowed)
__device__ float g_xn[kRows * kD];                 // 32 MB
__device__ float g_qkv[(size_t)kRows * kQKV];      // 96 MB
__device__ float g_attn[kRows * kInner];           // 32 MB

// ---------------------------------------------------------------------------
// LayerNorm: one block per row (D=1024, 256 threads, float4)
// ---------------------------------------------------------------------------
__global__ __launch_bounds__(256) void ln_kernel(
    const float* __restrict__ x, const float* __restrict__ gamma,
    const float* __restrict__ beta, float* __restrict__ xn) {
  const int row = blockIdx.x;
  const float* xr = x + (size_t)row * kD;
  const int i4 = threadIdx.x * 4;

  float4 v = *(const float4*)(xr + i4);
  float sum = v.x + v.y + v.z + v.w;
  float sq = v.x * v.x + v.y * v.y + v.z * v.z + v.w * v.w;

  __shared__ float s1[8], s2[8];
#pragma unroll
  for (int o = 16; o; o >>= 1) {
    sum += __shfl_xor_sync(0xffffffffu, sum, o);
    sq  += __shfl_xor_sync(0xffffffffu, sq, o);
  }
  const int w = threadIdx.x >> 5, l = threadIdx.x & 31;
  if (l == 0) { s1[w] = sum; s2[w] = sq; }
  __syncthreads();
  if (w == 0) {
    sum = (l < 8) ? s1[l] : 0.f;
    sq  = (l < 8) ? s2[l] : 0.f;
#pragma unroll
    for (int o = 4; o; o >>= 1) {
      sum += __shfl_xor_sync(0xffffffffu, sum, o);
      sq  += __shfl_xor_sync(0xffffffffu, sq, o);
    }
    if (l == 0) { s1[0] = sum; s2[0] = sq; }
  }
  __syncthreads();
  const float mu = s1[0] * (1.f / kD);
  const float var = s2[0] * (1.f / kD) - mu * mu;
  const float inv = rsqrtf(var + 1e-5f);

  float4 g = *(const float4*)(gamma + i4);
  float4 bt = *(const float4*)(beta + i4);
  float4 o;
  o.x = (v.x - mu) * inv * g.x + bt.x;
  o.y = (v.y - mu) * inv * g.y + bt.y;
  o.z = (v.z - mu) * inv * g.z + bt.z;
  o.w = (v.w - mu) * inv * g.w + bt.w;
  *(float4*)(xn + (size_t)row * kD + i4) = o;
}

// ---------------------------------------------------------------------------
// SGEMM: C[M,Nn] = A[M,K] * B[K,Nn] (+bias). 128x128 tile, 256 thr, 8x8/thr.
// All dims multiples of 128 / K multiple of 8; no bounds checks needed.
// ---------------------------------------------------------------------------
template <bool WITH_BIAS>
__global__ __launch_bounds__(256) void sgemm128(
    const float* __restrict__ A, const float* __restrict__ Bm,
    float* __restrict__ C, const float* __restrict__ bias,
    int M, int Nn, int K) {
  __shared__ float As[8][128];
  __shared__ float Bs[8][128];

  const int tid = threadIdx.x;
  const int tm = (tid >> 4) * 8;        // 0..120
  const int tn = (tid & 15) * 8;        // 0..120
  const int bm = blockIdx.y * 128;
  const int bn = blockIdx.x * 128;

  const int arow = tid >> 1;            // 0..127
  const int acol = (tid & 1) * 4;       // 0 or 4
  const int brow = tid >> 5;            // 0..7
  const int bcol = (tid & 31) * 4;      // 0..124

  const float* Aptr = A + (size_t)(bm + arow) * K + acol;
  const float* Bptr = Bm + (size_t)brow * Nn + bn + bcol;

  float acc[8][8];
#pragma unroll
  for (int i = 0; i < 8; i++)
#pragma unroll
    for (int j = 0; j < 8; j++) acc[i][j] = 0.f;

  for (int k0 = 0; k0 < K; k0 += 8) {
    float4 a4 = *(const float4*)(Aptr + k0);
    float4 b4 = *(const float4*)(Bptr + (size_t)k0 * Nn);
    As[acol + 0][arow] = a4.x;
    As[acol + 1][arow] = a4.y;
    As[acol + 2][arow] = a4.z;
    As[acol + 3][arow] = a4.w;
    *(float4*)&Bs[brow][bcol] = b4;
    __syncthreads();
#pragma unroll
    for (int kk = 0; kk < 8; kk++) {
      float af[8], bf[8];
#pragma unroll
      for (int i = 0; i < 8; i++) af[i] = As[kk][tm + i];
#pragma unroll
      for (int j = 0; j < 8; j++) bf[j] = Bs[kk][tn + j];
#pragma unroll
      for (int i = 0; i < 8; i++)
#pragma unroll
        for (int j = 0; j < 8; j++) acc[i][j] = fmaf(af[i], bf[j], acc[i][j]);
    }
    __syncthreads();
  }

#pragma unroll
  for (int i = 0; i < 8; i++) {
    const size_t crow = (size_t)(bm + tm + i) * Nn + bn + tn;
#pragma unroll
    for (int j = 0; j < 8; j += 4) {
      float4 v = make_float4(acc[i][j], acc[i][j + 1], acc[i][j + 2], acc[i][j + 3]);
      if (WITH_BIAS) {
        v.x += bias[bn + tn + j + 0];
        v.y += bias[bn + tn + j + 1];
        v.z += bias[bn + tn + j + 2];
        v.w += bias[bn + tn + j + 3];
      }
      *(float4*)&C[crow + j] = v;
    }
  }
}

// ---------------------------------------------------------------------------
// RoPE: in-place on q and k parts of qkv. One block per (b,n) row.
// pair (i, i+32) per head, i in [0,32).
// ---------------------------------------------------------------------------
__global__ __launch_bounds__(256) void rope_kernel(float* __restrict__ qkv) {
  const int row = blockIdx.x;          // 0..8191
  const int n = row & (kN - 1);
  __shared__ float invf[32];
  if (threadIdx.x < 32)
    invf[threadIdx.x] = powf(10000.0f, -(float)threadIdx.x / 32.0f);
  __syncthreads();

  float* base = qkv + (size_t)row * kQKV;
  for (int idx = threadIdx.x; idx < kH * 32; idx += blockDim.x) {
    const int h = idx >> 5;
    const int i = idx & 31;
    float s, c;
    sincosf((float)n * invf[i], &s, &c);
    float* q = base + h * kHD;
    float t1 = q[i], t2 = q[i + 32];
    q[i] = t1 * c - t2 * s;
    q[i + 32] = t2 * c + t1 * s;
    float* k = base + kInner + h * kHD;
    t1 = k[i]; t2 = k[i + 32];
    k[i] = t1 * c - t2 * s;
    k[i + 32] = t2 * c + t1 * s;
  }
}

// ---------------------------------------------------------------------------
// Attention: one thread per query row; 128 query rows per block;
// K/V tiles of 64 rows in smem (32 KB); streaming online softmax.
// ---------------------------------------------------------------------------
__global__ __launch_bounds__(128) void attn_kernel(
    const float* __restrict__ qkv, float* __restrict__ attn_out) {
  __shared__ float Ks[64][64];
  __shared__ float Vs[64][64];

  const int qt = blockIdx.x;           // 0..15
  const int bh = blockIdx.y;           // 0..63
  const int b = bh >> 4;
  const int h = bh & 15;
  const int t = threadIdx.x;
  const int qi = qt * 128 + t;

  const float* qp = qkv + (size_t)(b * kN + qi) * kQKV + h * kHD;
  float q[kHD], O[kHD];
#pragma unroll
  for (int d = 0; d < kHD; d++) { q[d] = qp[d]; O[d] = 0.f; }
  float m = -1e30f, l = 0.f;

  for (int kt = 0; kt < kN / 64; kt++) {
    __syncthreads();  // protect previous tile from overwrite
    const float* kbase = qkv + (size_t)(b * kN + kt * 64) * kQKV + h * kHD;
#pragma unroll
    for (int it = 0; it < 8; it++) {
      const int idx = it * 128 + t;    // 0..1023
      const int r = idx >> 4;
      const int c = (idx & 15) * 4;
      *(float4*)&Ks[r][c] = *(const float4*)(kbase + (size_t)r * kQKV + kInner + c);
      *(float4*)&Vs[r][c] = *(const float4*)(kbase + (size_t)r * kQKV + 2 * kInner + c);
    }
    __syncthreads();

    for (int j = 0; j < 64; j++) {
      float s0 = 0.f, s1 = 0.f, s2 = 0.f, s3 = 0.f;
#pragma unroll
      for (int d = 0; d < kHD; d += 4) {
        s0 = fmaf(q[d + 0], Ks[j][d + 0], s0);
        s1 = fmaf(q[d + 1], Ks[j][d + 1], s1);
        s2 = fmaf(q[d + 2], Ks[j][d + 2], s2);
        s3 = fmaf(q[d + 3], Ks[j][d + 3], s3);
      }
      float s = ((s0 + s1) + (s2 + s3)) * 0.125f;   // * HD^-0.5
      if (s > m) {
        const float corr = __expf(m - s);
        l *= corr;
#pragma unroll
        for (int d = 0; d < kHD; d++) O[d] *= corr;
        m = s;
      }
      const float p = __expf(s - m);
      l += p;
#pragma unroll
      for (int d = 0; d < kHD; d++) O[d] = fmaf(p, Vs[j][d], O[d]);
    }
  }

  const float invl = 1.f / l;
  float* op = attn_out + (size_t)(b * kN + qi) * kInner + h * kHD;
#pragma unroll
  for (int d = 0; d < kHD; d++) op[d] = O[d] * invl;
}

// ---------------------------------------------------------------------------
// Launch
// ---------------------------------------------------------------------------
extern "C" void kernel_launch(void* const* d_in, const int* in_sizes, int n_in,
                              void* d_out, int out_size) {
  const float* x      = (const float*)d_in[0];
  const float* gamma  = (const float*)d_in[1];
  const float* beta   = (const float*)d_in[2];
  const float* w_qkv  = (const float*)d_in[3];
  const float* w_out  = (const float*)d_in[4];
  const float* b_out  = (const float*)d_in[5];
  float* out = (float*)d_out;

  void* p;
  cudaGetSymbolAddress(&p, g_xn);
  float* xn = (float*)p;
  cudaGetSymbolAddress(&p, g_qkv);
  float* qkv = (float*)p;
  cudaGetSymbolAddress(&p, g_attn);
  float* attn = (float*)p;

  ln_kernel<<<kRows, 256>>>(x, gamma, beta, xn);

  sgemm128<false><<<dim3(kQKV / 128, kRows / 128), 256>>>(
      xn, w_qkv, qkv, nullptr, kRows, kQKV, kD);

  rope_kernel<<<kRows, 256>>>(qkv);

  attn_kernel<<<dim3(kN / 128, kB * kH), 128>>>(qkv, attn);

  sgemm128<true><<<dim3(kD / 128, kRows / 128), 256>>>(
      attn, w_out, out, b_out, kRows, kD, kInner);
}